// round 5
// baseline (speedup 1.0000x reference)
#include <cuda_runtime.h>
#include <math.h>
#include <stdint.h>

#define B_  4
#define L_  2048
#define H_  12
#define HD_ 64
#define DM_ 768
#define M_  (B_*L_)   // 8192

// Scratch (allocation-free rule: __device__ globals)
__device__ float g_q[B_*H_*L_*HD_];
__device__ float g_k[B_*H_*L_*HD_];
__device__ float g_v[B_*H_*L_*HD_];
__device__ float g_o[M_*DM_];
__device__ float g_x[M_*DM_];          // tf32-rounded hidden_states
__device__ float g_w[4][DM_*DM_];      // tf32-rounded wq,wk,wv,wo

// ---------------- helpers ----------------
__device__ __forceinline__ float to_tf32(float x) {
    uint32_t o; asm("cvt.rna.tf32.f32 %0, %1;" : "=r"(o) : "f"(x));
    return __uint_as_float(o);
}
__device__ __forceinline__ uint32_t smem_u32(const void* p) {
    uint32_t a;
    asm("{ .reg .u64 t; cvta.to.shared.u64 t, %1; cvt.u32.u64 %0, t; }" : "=r"(a) : "l"(p));
    return a;
}
__device__ __forceinline__ void cp_async16(uint32_t saddr, const void* gptr) {
    asm volatile("cp.async.cg.shared.global [%0], [%1], 16;\n" :: "r"(saddr), "l"(gptr));
}
__device__ __forceinline__ void cp_commit() { asm volatile("cp.async.commit_group;\n"); }
template<int N>
__device__ __forceinline__ void cp_wait() {
    asm volatile("cp.async.wait_group %0;\n" :: "n"(N));
}
__device__ __forceinline__ void mma_tf32(float c[4], const uint32_t a[4], const uint32_t b[2]) {
    asm volatile(
        "mma.sync.aligned.m16n8k8.row.col.f32.tf32.tf32.f32 "
        "{%0,%1,%2,%3}, {%4,%5,%6,%7}, {%8,%9}, {%0,%1,%2,%3};\n"
        : "+f"(c[0]), "+f"(c[1]), "+f"(c[2]), "+f"(c[3])
        : "r"(a[0]), "r"(a[1]), "r"(a[2]), "r"(a[3]), "r"(b[0]), "r"(b[1]));
}

// SW128 swizzled smem access for 128B rows of 32 floats
#define SWZ(x) ((x) ^ ((((uint32_t)(x)) >> 3) & 0x70u))
__device__ __forceinline__ uint32_t lds_swz(const char* base, int row, int k) {
    const uint32_t off = (uint32_t)(row*128 + k*4) ^ (((uint32_t)row & 7u) << 4);
    return *(const uint32_t*)(base + off);
}

// ---------------- prepass: round X and W to tf32 (rna) ----------------
__global__ __launch_bounds__(256) void prepass(const float4* __restrict__ hs,
    const float4* __restrict__ wq, const float4* __restrict__ wk,
    const float4* __restrict__ wv, const float4* __restrict__ wo)
{
    const int stride = gridDim.x * blockDim.x;
    const int i0 = blockIdx.x * blockDim.x + threadIdx.x;
    float4* gx = (float4*)g_x;
    for (int i = i0; i < M_*DM_/4; i += stride) {
        float4 t = hs[i];
        gx[i] = make_float4(to_tf32(t.x), to_tf32(t.y), to_tf32(t.z), to_tf32(t.w));
    }
    const float4* src[4] = {wq, wk, wv, wo};
    #pragma unroll
    for (int w = 0; w < 4; w++) {
        float4* dw = (float4*)g_w[w];
        const float4* s = src[w];
        for (int i = i0; i < DM_*DM_/4; i += stride) {
            float4 t = s[i];
            dw[i] = make_float4(to_tf32(t.x), to_tf32(t.y), to_tf32(t.z), to_tf32(t.w));
        }
    }
}

// ---------------- mma.sync tf32 GEMM: C[m,n] = sum_k A[m,k]*W[n,k] + bias[n] ----------------
// 128 threads / 4 warps (2m x 2n), warptile 64x64, CTA 128x128, GBK=32.
// A/B tiles: SW128-swizzled 128B rows (32 floats), double buffered.
#define GBK 32
#define GTILE 16384                     // 128 rows * 128B
#define G_SMEM_TOT (4*GTILE + 1024 + 1024)

template<bool SCATTER>
__device__ __forceinline__ void tc_gemm(const float* __restrict__ A,
                                        const float* __restrict__ W,
                                        const float* __restrict__ bias,
                                        float* __restrict__ C)
{
    extern __shared__ char gsm[];
    char* base = (char*)(((uintptr_t)gsm + 1023u) & ~(uintptr_t)1023u);
    char* sA[2] = { base,            base + GTILE };
    char* sB[2] = { base + 2*GTILE,  base + 3*GTILE };
    float* bias_s = (float*)(base + 4*GTILE);

    const int tid = threadIdx.x;
    const int wid = tid >> 5;
    const int lane = tid & 31;
    const int grp = lane >> 2;
    const int qid = lane & 3;
    const int wm = (wid & 1) * 64;
    const int wn = (wid >> 1) * 64;
    const int bm = blockIdx.y * 128;
    const int bn = blockIdx.x * 128;

    if (tid < 128) bias_s[tid] = bias[bn + tid];

    float acc[4][8][4];
    #pragma unroll
    for (int mi = 0; mi < 4; mi++)
        #pragma unroll
        for (int ni = 0; ni < 8; ni++)
            #pragma unroll
            for (int e = 0; e < 4; e++) acc[mi][ni][e] = 0.f;

    // fill tile (A and B) for k-chunk c into buffer b
    const int frow = tid >> 3;          // 0..15 base row (x8 iters covers 128)
    const int fsg  = tid & 7;           // 16B chunk in row
    uint32_t sAu[2] = { smem_u32(sA[0]), smem_u32(sA[1]) };
    uint32_t sBu[2] = { smem_u32(sB[0]), smem_u32(sB[1]) };

    #define G_FILL(c, b) do { \
        const float* Ab = A + (size_t)bm * DM_ + (c)*GBK; \
        const float* Wb = W + (size_t)bn * DM_ + (c)*GBK; \
        _Pragma("unroll") \
        for (int it = 0; it < 8; it++) { \
            const int r = frow + it*16; \
            cp_async16(sAu[b] + SWZ(r*128 + fsg*16), Ab + (size_t)r*DM_ + fsg*4); \
            cp_async16(sBu[b] + SWZ(r*128 + fsg*16), Wb + (size_t)r*DM_ + fsg*4); \
        } \
        cp_commit(); \
    } while (0)

    G_FILL(0, 0);

    const int NC = DM_/GBK;   // 24
    int cur = 0;
    for (int c = 0; c < NC; c++) {
        if (c + 1 < NC) { G_FILL(c + 1, cur ^ 1); cp_wait<1>(); }
        else            { cp_wait<0>(); }
        __syncthreads();

        const char* Ac = sA[cur];
        const char* Bc = sB[cur];
        #pragma unroll
        for (int kb = 0; kb < 4; kb++) {
            const int kk = kb*8;
            uint32_t af[4][4];
            #pragma unroll
            for (int mi = 0; mi < 4; mi++) {
                const int r0 = wm + mi*16 + grp;
                af[mi][0] = lds_swz(Ac, r0,     kk + qid);
                af[mi][1] = lds_swz(Ac, r0 + 8, kk + qid);
                af[mi][2] = lds_swz(Ac, r0,     kk + qid + 4);
                af[mi][3] = lds_swz(Ac, r0 + 8, kk + qid + 4);
            }
            #pragma unroll
            for (int ni = 0; ni < 8; ni++) {
                const int rn = wn + ni*8 + grp;
                uint32_t bf[2];
                bf[0] = lds_swz(Bc, rn, kk + qid);
                bf[1] = lds_swz(Bc, rn, kk + qid + 4);
                #pragma unroll
                for (int mi = 0; mi < 4; mi++)
                    mma_tf32(acc[mi][ni], af[mi], bf);
            }
        }
        __syncthreads();
        cur ^= 1;
    }
    #undef G_FILL

    // epilogue
    #pragma unroll
    for (int mi = 0; mi < 4; mi++) {
        #pragma unroll
        for (int half = 0; half < 2; half++) {
            const int m  = bm + wm + mi*16 + grp + half*8;
            const int bb = m >> 11;
            const int l  = m & (L_ - 1);
            #pragma unroll
            for (int ni = 0; ni < 8; ni++) {
                const int nl = wn + ni*8 + 2*qid;
                float v0 = acc[mi][ni][half*2 + 0] + bias_s[nl];
                float v1 = acc[mi][ni][half*2 + 1] + bias_s[nl + 1];
                if (SCATTER) {
                    const int n = bn + nl;
                    const int hh = n / HD_;
                    const int d  = n & (HD_ - 1);
                    // round so flash/out mma inputs are exact tf32
                    *(float2*)&C[(((size_t)bb*H_ + hh)*L_ + l)*HD_ + d] =
                        make_float2(to_tf32(v0), to_tf32(v1));
                } else {
                    *(float2*)&C[(size_t)m*DM_ + bn + nl] = make_float2(v0, v1);
                }
            }
        }
    }
}

__global__ __launch_bounds__(128, 3) void qkv_gemm(const float* __restrict__ bq,
                                                   const float* __restrict__ bk,
                                                   const float* __restrict__ bv)
{
    const int z = blockIdx.z;
    const float* W = g_w[z];
    const float* bias = (z == 0) ? bq : (z == 1) ? bk : bv;
    float* out = (z == 0) ? g_q : (z == 1) ? g_k : g_v;
    tc_gemm<true>(g_x, W, bias, out);
}

__global__ __launch_bounds__(128, 3) void out_gemm(const float* __restrict__ bo,
                                                   float* __restrict__ out)
{
    tc_gemm<false>(g_o, g_w[3], bo, out);
}

// ============ causal flash attention (tf32 mma.sync, cp.async double-buffered K/V) ============
// Q,K,V: [B,H,L,HD] (tf32-rounded); O: [B,L,H,HD]. FQ=64 rows/CTA, 4 warps x 16 rows.
#define FQ   64
#define KPAD 68    // linear K row stride: bank = grp*4+qid, conflict-free
#define VPAD 72    // linear V row stride: bank = qid*8+grp, conflict-free
#define F_SMEM ((2*64*KPAD + 2*64*VPAD) * 4)   // 71680

__global__ __launch_bounds__(128, 3) void flash_kernel()
{
    extern __shared__ float fsm[];
    float* Ksb[2] = { fsm,             fsm + 64*KPAD };
    float* Vsb[2] = { fsm + 2*64*KPAD, fsm + 2*64*KPAD + 64*VPAD };
    const uint32_t Ku[2] = { smem_u32(Ksb[0]), smem_u32(Ksb[1]) };
    const uint32_t Vu[2] = { smem_u32(Vsb[0]), smem_u32(Vsb[1]) };

    const int tid  = threadIdx.x;
    const int wid  = tid >> 5;
    const int lane = tid & 31;
    const int grp  = lane >> 2;
    const int qid  = lane & 3;

    const int qt = (int)gridDim.x - 1 - (int)blockIdx.x;  // descending work
    const int h  = blockIdx.y % H_;
    const int b  = blockIdx.y / H_;

    const float* Qb = g_q + (size_t)(b*H_ + h) * L_ * HD_;
    const float* Kb = g_k + (size_t)(b*H_ + h) * L_ * HD_;
    const float* Vb = g_v + (size_t)(b*H_ + h) * L_ * HD_;

    const int qrow0 = qt*FQ + wid*16;
    const float scale = 0.125f;   // exact power of 2: preserves tf32-ness

    const int frow = tid >> 4;    // 0..7 base row (x8 iters covers 64)
    const int fc16 = tid & 15;    // 16B chunk in 256B row

    #define F_FILL(kt, bf) do { \
        const float* ksrc = Kb + (size_t)(kt)*FQ*HD_; \
        const float* vsrc = Vb + (size_t)(kt)*FQ*HD_; \
        _Pragma("unroll") \
        for (int it = 0; it < 8; it++) { \
            const int r = frow + it*8; \
            cp_async16(Ku[bf] + r*(KPAD*4) + fc16*16, ksrc + (size_t)r*HD_ + fc16*4); \
            cp_async16(Vu[bf] + r*(VPAD*4) + fc16*16, vsrc + (size_t)r*HD_ + fc16*4); \
        } \
        cp_commit(); \
    } while (0)

    uint32_t qa[8][4];
    #pragma unroll
    for (int kc = 0; kc < 8; kc++) {
        qa[kc][0] = __float_as_uint(scale * Qb[(size_t)(qrow0 + grp    )*HD_ + kc*8 + qid    ]);
        qa[kc][1] = __float_as_uint(scale * Qb[(size_t)(qrow0 + grp + 8)*HD_ + kc*8 + qid    ]);
        qa[kc][2] = __float_as_uint(scale * Qb[(size_t)(qrow0 + grp    )*HD_ + kc*8 + qid + 4]);
        qa[kc][3] = __float_as_uint(scale * Qb[(size_t)(qrow0 + grp + 8)*HD_ + kc*8 + qid + 4]);
    }

    float o[8][4];
    #pragma unroll
    for (int ni = 0; ni < 8; ni++)
        #pragma unroll
        for (int e = 0; e < 4; e++) o[ni][e] = 0.f;
    float m0 = -1e30f, m1 = -1e30f, l0 = 0.f, l1 = 0.f;

    F_FILL(0, 0);
    int buf = 0;
    for (int kt = 0; kt <= qt; kt++) {
        if (kt < qt) { F_FILL(kt + 1, buf ^ 1); cp_wait<1>(); }
        else         { cp_wait<0>(); }
        __syncthreads();
        const float* Ks = Ksb[buf];
        const float* Vs = Vsb[buf];

        // ---- S = Q K^T ----
        float sc[8][4];
        #pragma unroll
        for (int ni = 0; ni < 8; ni++)
            #pragma unroll
            for (int e = 0; e < 4; e++) sc[ni][e] = 0.f;

        #pragma unroll
        for (int kc = 0; kc < 8; kc++) {
            #pragma unroll
            for (int ni = 0; ni < 8; ni++) {
                const float* kr = &Ks[(ni*8 + grp)*KPAD + kc*8 + qid];
                uint32_t bfr[2] = { __float_as_uint(kr[0]), __float_as_uint(kr[4]) };
                mma_tf32(sc[ni], qa[kc], bfr);
            }
        }

        if (kt == qt) {
            const int r0 = qrow0 + grp;
            const int r1 = r0 + 8;
            #pragma unroll
            for (int ni = 0; ni < 8; ni++) {
                const int kg = kt*FQ + ni*8 + 2*qid;
                if (kg     > r0) sc[ni][0] = -1e30f;
                if (kg + 1 > r0) sc[ni][1] = -1e30f;
                if (kg     > r1) sc[ni][2] = -1e30f;
                if (kg + 1 > r1) sc[ni][3] = -1e30f;
            }
        }

        // ---- online softmax ----
        float tm0 = -1e30f, tm1 = -1e30f;
        #pragma unroll
        for (int ni = 0; ni < 8; ni++) {
            tm0 = fmaxf(tm0, fmaxf(sc[ni][0], sc[ni][1]));
            tm1 = fmaxf(tm1, fmaxf(sc[ni][2], sc[ni][3]));
        }
        tm0 = fmaxf(tm0, __shfl_xor_sync(0xffffffffu, tm0, 1));
        tm0 = fmaxf(tm0, __shfl_xor_sync(0xffffffffu, tm0, 2));
        tm1 = fmaxf(tm1, __shfl_xor_sync(0xffffffffu, tm1, 1));
        tm1 = fmaxf(tm1, __shfl_xor_sync(0xffffffffu, tm1, 2));

        const float mn0 = fmaxf(m0, tm0);
        const float mn1 = fmaxf(m1, tm1);
        const float corr0 = __expf(m0 - mn0);
        const float corr1 = __expf(m1 - mn1);
        m0 = mn0; m1 = mn1;

        float ps0 = 0.f, ps1 = 0.f;
        #pragma unroll
        for (int ni = 0; ni < 8; ni++) {
            sc[ni][0] = to_tf32(__expf(sc[ni][0] - mn0));
            sc[ni][1] = to_tf32(__expf(sc[ni][1] - mn0));
            sc[ni][2] = to_tf32(__expf(sc[ni][2] - mn1));
            sc[ni][3] = to_tf32(__expf(sc[ni][3] - mn1));
            ps0 += sc[ni][0] + sc[ni][1];
            ps1 += sc[ni][2] + sc[ni][3];
        }
        ps0 += __shfl_xor_sync(0xffffffffu, ps0, 1);
        ps0 += __shfl_xor_sync(0xffffffffu, ps0, 2);
        ps1 += __shfl_xor_sync(0xffffffffu, ps1, 1);
        ps1 += __shfl_xor_sync(0xffffffffu, ps1, 2);
        l0 = l0*corr0 + ps0;
        l1 = l1*corr1 + ps1;

        #pragma unroll
        for (int ni = 0; ni < 8; ni++) {
            o[ni][0] *= corr0; o[ni][1] *= corr0;
            o[ni][2] *= corr1; o[ni][3] *= corr1;
        }

        // ---- O += P V (P via shuffle: c-layout -> a-layout) ----
        const int sA_ = (lane & ~3) | (qid >> 1);
        const bool hiq = (qid & 1);
        #pragma unroll
        for (int kc = 0; kc < 8; kc++) {
            float e0A = __shfl_sync(0xffffffffu, sc[kc][0], sA_);
            float e1A = __shfl_sync(0xffffffffu, sc[kc][1], sA_);
            float e2A = __shfl_sync(0xffffffffu, sc[kc][2], sA_);
            float e3A = __shfl_sync(0xffffffffu, sc[kc][3], sA_);
            float e0B = __shfl_sync(0xffffffffu, sc[kc][0], sA_ + 2);
            float e1B = __shfl_sync(0xffffffffu, sc[kc][1], sA_ + 2);
            float e2B = __shfl_sync(0xffffffffu, sc[kc][2], sA_ + 2);
            float e3B = __shfl_sync(0xffffffffu, sc[kc][3], sA_ + 2);
            uint32_t pa[4];
            pa[0] = __float_as_uint(hiq ? e1A : e0A);
            pa[1] = __float_as_uint(hiq ? e3A : e2A);
            pa[2] = __float_as_uint(hiq ? e1B : e0B);
            pa[3] = __float_as_uint(hiq ? e3B : e2B);
            #pragma unroll
            for (int ni = 0; ni < 8; ni++) {
                const float* vr = &Vs[(kc*8 + qid)*VPAD + ni*8 + grp];
                uint32_t bfr[2] = { __float_as_uint(vr[0]), __float_as_uint(vr[4*VPAD]) };
                mma_tf32(o[ni], pa, bfr);
            }
        }
        __syncthreads();
        buf ^= 1;
    }
    #undef F_FILL

    // ---- normalize + store O as [B, L, H, HD], tf32-rounded for out_gemm ----
    const float inv0 = 1.f / l0;
    const float inv1 = 1.f / l1;
    const int r0 = qrow0 + grp;
    const int r1 = r0 + 8;
    float* O0 = g_o + (((size_t)(b*L_ + r0))*H_ + h) * HD_;
    float* O1 = g_o + (((size_t)(b*L_ + r1))*H_ + h) * HD_;
    #pragma unroll
    for (int ni = 0; ni < 8; ni++) {
        const int col = ni*8 + 2*qid;
        *(float2*)&O0[col] = make_float2(to_tf32(o[ni][0]*inv0), to_tf32(o[ni][1]*inv0));
        *(float2*)&O1[col] = make_float2(to_tf32(o[ni][2]*inv1), to_tf32(o[ni][3]*inv1));
    }
}

// ============ launch ============
extern "C" void kernel_launch(void* const* d_in, const int* in_sizes, int n_in,
                              void* d_out, int out_size)
{
    const float* hs = (const float*)d_in[0];
    const float* wq = (const float*)d_in[1];
    const float* bq = (const float*)d_in[2];
    const float* wk = (const float*)d_in[3];
    const float* bk = (const float*)d_in[4];
    const float* wv = (const float*)d_in[5];
    const float* bv = (const float*)d_in[6];
    const float* wo = (const float*)d_in[7];
    const float* bo = (const float*)d_in[8];
    float* out = (float*)d_out;

    cudaFuncSetAttribute(qkv_gemm, cudaFuncAttributeMaxDynamicSharedMemorySize, G_SMEM_TOT);
    cudaFuncSetAttribute(out_gemm, cudaFuncAttributeMaxDynamicSharedMemorySize, G_SMEM_TOT);
    cudaFuncSetAttribute(flash_kernel, cudaFuncAttributeMaxDynamicSharedMemorySize, F_SMEM);

    prepass<<<512, 256>>>((const float4*)hs, (const float4*)wq, (const float4*)wk,
                          (const float4*)wv, (const float4*)wo);
    qkv_gemm<<<dim3(DM_/128, M_/128, 3), 128, G_SMEM_TOT>>>(bq, bk, bv);
    flash_kernel<<<dim3(L_/FQ, H_*B_), 128, F_SMEM>>>();
    out_gemm<<<dim3(DM_/128, M_/128), 128, G_SMEM_TOT>>>(bo, out);
}

// round 6
// speedup vs baseline: 1.5779x; 1.5779x over previous
#include <cuda_runtime.h>
#include <math.h>
#include <stdint.h>

#define B_  4
#define L_  2048
#define H_  12
#define HD_ 64
#define DM_ 768
#define M_  (B_*L_)   // 8192

// Scratch (allocation-free rule: __device__ globals)
__device__ float g_q[B_*H_*L_*HD_];
__device__ float g_k[B_*H_*L_*HD_];
__device__ float g_v[B_*H_*L_*HD_];
__device__ float g_o[M_*DM_];
__device__ float g_x[M_*DM_];          // tf32-rounded hidden_states
__device__ float g_w[4][DM_*DM_];      // tf32-rounded wq,wk,wv,wo

// ---------------- helpers ----------------
__device__ __forceinline__ float to_tf32(float x) {
    uint32_t o; asm("cvt.rna.tf32.f32 %0, %1;" : "=r"(o) : "f"(x));
    return __uint_as_float(o);
}
__device__ __forceinline__ uint32_t smem_u32(const void* p) {
    uint32_t a;
    asm("{ .reg .u64 t; cvta.to.shared.u64 t, %1; cvt.u32.u64 %0, t; }" : "=r"(a) : "l"(p));
    return a;
}
__device__ __forceinline__ void cp_async16(uint32_t saddr, const void* gptr) {
    asm volatile("cp.async.ca.shared.global [%0], [%1], 16;\n" :: "r"(saddr), "l"(gptr));
}
__device__ __forceinline__ void cp_commit() { asm volatile("cp.async.commit_group;\n"); }
template<int N>
__device__ __forceinline__ void cp_wait() {
    asm volatile("cp.async.wait_group %0;\n" :: "n"(N));
}
__device__ __forceinline__ void mma_tf32(float c[4], const uint32_t a[4], const uint32_t b[2]) {
    asm volatile(
        "mma.sync.aligned.m16n8k8.row.col.f32.tf32.tf32.f32 "
        "{%0,%1,%2,%3}, {%4,%5,%6,%7}, {%8,%9}, {%0,%1,%2,%3};\n"
        : "+f"(c[0]), "+f"(c[1]), "+f"(c[2]), "+f"(c[3])
        : "r"(a[0]), "r"(a[1]), "r"(a[2]), "r"(a[3]), "r"(b[0]), "r"(b[1]));
}

// ---------------- prepass: round X and W to tf32 (rna) ----------------
__global__ __launch_bounds__(256) void prepass(const float4* __restrict__ hs,
    const float4* __restrict__ wq, const float4* __restrict__ wk,
    const float4* __restrict__ wv, const float4* __restrict__ wo)
{
    const int stride = gridDim.x * blockDim.x;
    const int i0 = blockIdx.x * blockDim.x + threadIdx.x;
    float4* gx = (float4*)g_x;
    for (int i = i0; i < M_*DM_/4; i += stride) {
        float4 t = hs[i];
        gx[i] = make_float4(to_tf32(t.x), to_tf32(t.y), to_tf32(t.z), to_tf32(t.w));
    }
    const float4* src[4] = {wq, wk, wv, wo};
    #pragma unroll
    for (int w = 0; w < 4; w++) {
        float4* dw = (float4*)g_w[w];
        const float4* s = src[w];
        for (int i = i0; i < DM_*DM_/4; i += stride) {
            float4 t = s[i];
            dw[i] = make_float4(to_tf32(t.x), to_tf32(t.y), to_tf32(t.z), to_tf32(t.w));
        }
    }
}

// ---------------- mma.sync tf32 GEMM: C[m,n] = sum_k A[m,k]*W[n,k] + bias[n] ----------------
// CTA 128x256, 256 threads / 8 warps (2m x 4n), warptile 64x64, GBK=16.
// smem (floats): As[2][128*20] @0, Ws[2][256*20] @5120, bias @15360. Total 15616 fl = 62464 B.
#define GBK  16
#define GPAD 20
#define AS_OFF(b)  ((b)*2560)
#define WS_OFF(b)  (5120 + (b)*5120)
#define BIAS_OFF   15360
#define G_SMEM_TOT (15616*4)

template<bool SCATTER>
__device__ __forceinline__ void tc_gemm(const float* __restrict__ A,
                                        const float* __restrict__ W,
                                        const float* __restrict__ bias,
                                        float* __restrict__ C, int bn)
{
    extern __shared__ float gsm[];

    const int tid = threadIdx.x;          // 0..255
    const int wid = tid >> 5;
    const int lane = tid & 31;
    const int grp = lane >> 2;
    const int qid = lane & 3;
    const int wm = (wid & 1) * 64;
    const int wn = (wid >> 1) * 64;
    const int bm = blockIdx.y * 128;

    gsm[BIAS_OFF + tid] = bias[bn + tid];

    float acc[4][8][4];
    #pragma unroll
    for (int mi = 0; mi < 4; mi++)
        #pragma unroll
        for (int ni = 0; ni < 8; ni++)
            #pragma unroll
            for (int e = 0; e < 4; e++) acc[mi][ni][e] = 0.f;

    const int lr = tid >> 2;              // 0..63
    const int c4 = (tid & 3) * 4;         // 0,4,8,12

    #define G_FILL(c, b) do { \
        const float* Ab = A + (size_t)bm * DM_ + (c)*GBK; \
        const float* Wb = W + (size_t)bn * DM_ + (c)*GBK; \
        _Pragma("unroll") \
        for (int it = 0; it < 2; it++) { \
            const int r = lr + it*64; \
            cp_async16(smem_u32(&gsm[AS_OFF(b) + r*GPAD + c4]), Ab + (size_t)r*DM_ + c4); \
        } \
        _Pragma("unroll") \
        for (int it = 0; it < 4; it++) { \
            const int r = lr + it*64; \
            cp_async16(smem_u32(&gsm[WS_OFF(b) + r*GPAD + c4]), Wb + (size_t)r*DM_ + c4); \
        } \
        cp_commit(); \
    } while (0)

    G_FILL(0, 0);

    const int NC = DM_/GBK;   // 48
    int cur = 0;
    for (int c = 0; c < NC; c++) {
        cp_wait<0>();
        __syncthreads();
        if (c + 1 < NC) G_FILL(c + 1, cur ^ 1);

        const int ab = AS_OFF(cur);
        const int wb = WS_OFF(cur);
        #pragma unroll
        for (int kb = 0; kb < 2; kb++) {
            const int kk = kb*8;
            uint32_t af[4][4];
            #pragma unroll
            for (int mi = 0; mi < 4; mi++) {
                const int r0 = wm + mi*16 + grp;
                af[mi][0] = __float_as_uint(gsm[ab + (r0    )*GPAD + kk + qid    ]);
                af[mi][1] = __float_as_uint(gsm[ab + (r0 + 8)*GPAD + kk + qid    ]);
                af[mi][2] = __float_as_uint(gsm[ab + (r0    )*GPAD + kk + qid + 4]);
                af[mi][3] = __float_as_uint(gsm[ab + (r0 + 8)*GPAD + kk + qid + 4]);
            }
            #pragma unroll
            for (int ni = 0; ni < 8; ni++) {
                const int rn = wn + ni*8 + grp;
                uint32_t bf[2];
                bf[0] = __float_as_uint(gsm[wb + rn*GPAD + kk + qid    ]);
                bf[1] = __float_as_uint(gsm[wb + rn*GPAD + kk + qid + 4]);
                #pragma unroll
                for (int mi = 0; mi < 4; mi++)
                    mma_tf32(acc[mi][ni], af[mi], bf);
            }
        }
        cur ^= 1;
        __syncthreads();
    }
    #undef G_FILL

    // epilogue
    #pragma unroll
    for (int mi = 0; mi < 4; mi++) {
        #pragma unroll
        for (int half = 0; half < 2; half++) {
            const int m  = bm + wm + mi*16 + grp + half*8;
            const int bb = m >> 11;
            const int l  = m & (L_ - 1);
            #pragma unroll
            for (int ni = 0; ni < 8; ni++) {
                const int nl = wn + ni*8 + 2*qid;
                float v0 = acc[mi][ni][half*2 + 0] + gsm[BIAS_OFF + nl];
                float v1 = acc[mi][ni][half*2 + 1] + gsm[BIAS_OFF + nl + 1];
                if (SCATTER) {
                    const int n = bn + nl;       // col within this weight's 768
                    const int hh = n >> 6;
                    const int d  = n & 63;
                    // round so flash / out_gemm mma inputs are exact tf32
                    *(float2*)&C[(((size_t)bb*H_ + hh)*L_ + l)*HD_ + d] =
                        make_float2(to_tf32(v0), to_tf32(v1));
                } else {
                    *(float2*)&C[(size_t)m*DM_ + bn + nl] = make_float2(v0, v1);
                }
            }
        }
    }
}

__global__ __launch_bounds__(256) void qkv_gemm(const float* __restrict__ bq,
                                                const float* __restrict__ bk,
                                                const float* __restrict__ bv)
{
    const int z  = blockIdx.x / 3;                 // weight select
    const int bn = (blockIdx.x % 3) * 256;         // col tile within weight
    const float* bias = (z == 0) ? bq : (z == 1) ? bk : bv;
    float* out = (z == 0) ? g_q : (z == 1) ? g_k : g_v;
    tc_gemm<true>(g_x, g_w[z], bias, out, bn);
}

__global__ __launch_bounds__(256) void out_gemm(const float* __restrict__ bo,
                                                float* __restrict__ out)
{
    tc_gemm<false>(g_o, g_w[3], bo, out, blockIdx.x * 256);
}

// ============ causal flash attention (tf32 mma.sync, cp.async double-buffered K/V) ============
// Q,K,V: [B,H,L,HD] (tf32-rounded); O: [B,L,H,HD]. FQ=64 rows/CTA, 4 warps x 16 rows.
#define FQ   64
#define KPAD 68    // linear K row stride: bank = grp*4+qid, conflict-free
#define VPAD 72    // linear V row stride: bank = qid*8+grp, conflict-free
#define F_SMEM ((2*64*KPAD + 2*64*VPAD) * 4)   // 71680

__global__ __launch_bounds__(128, 3) void flash_kernel()
{
    extern __shared__ float fsm[];
    float* Ksb[2] = { fsm,             fsm + 64*KPAD };
    float* Vsb[2] = { fsm + 2*64*KPAD, fsm + 2*64*KPAD + 64*VPAD };
    const uint32_t Ku[2] = { smem_u32(Ksb[0]), smem_u32(Ksb[1]) };
    const uint32_t Vu[2] = { smem_u32(Vsb[0]), smem_u32(Vsb[1]) };

    const int tid  = threadIdx.x;
    const int wid  = tid >> 5;
    const int lane = tid & 31;
    const int grp  = lane >> 2;
    const int qid  = lane & 3;

    const int qt = (int)gridDim.x - 1 - (int)blockIdx.x;  // descending work
    const int h  = blockIdx.y % H_;
    const int b  = blockIdx.y / H_;

    const float* Qb = g_q + (size_t)(b*H_ + h) * L_ * HD_;
    const float* Kb = g_k + (size_t)(b*H_ + h) * L_ * HD_;
    const float* Vb = g_v + (size_t)(b*H_ + h) * L_ * HD_;

    const int qrow0 = qt*FQ + wid*16;
    const float scale = 0.125f;   // exact power of 2: preserves tf32-ness

    const int frow = tid >> 4;    // 0..7 base row (x8 iters covers 64)
    const int fc16 = tid & 15;    // 16B chunk in 256B row

    #define F_FILL(kt, bf) do { \
        const float* ksrc = Kb + (size_t)(kt)*FQ*HD_; \
        const float* vsrc = Vb + (size_t)(kt)*FQ*HD_; \
        _Pragma("unroll") \
        for (int it = 0; it < 8; it++) { \
            const int r = frow + it*8; \
            cp_async16(Ku[bf] + r*(KPAD*4) + fc16*16, ksrc + (size_t)r*HD_ + fc16*4); \
            cp_async16(Vu[bf] + r*(VPAD*4) + fc16*16, vsrc + (size_t)r*HD_ + fc16*4); \
        } \
        cp_commit(); \
    } while (0)

    uint32_t qa[8][4];
    #pragma unroll
    for (int kc = 0; kc < 8; kc++) {
        qa[kc][0] = __float_as_uint(scale * Qb[(size_t)(qrow0 + grp    )*HD_ + kc*8 + qid    ]);
        qa[kc][1] = __float_as_uint(scale * Qb[(size_t)(qrow0 + grp + 8)*HD_ + kc*8 + qid    ]);
        qa[kc][2] = __float_as_uint(scale * Qb[(size_t)(qrow0 + grp    )*HD_ + kc*8 + qid + 4]);
        qa[kc][3] = __float_as_uint(scale * Qb[(size_t)(qrow0 + grp + 8)*HD_ + kc*8 + qid + 4]);
    }

    float o[8][4];
    #pragma unroll
    for (int ni = 0; ni < 8; ni++)
        #pragma unroll
        for (int e = 0; e < 4; e++) o[ni][e] = 0.f;
    float m0 = -1e30f, m1 = -1e30f, l0 = 0.f, l1 = 0.f;

    F_FILL(0, 0);
    int buf = 0;
    for (int kt = 0; kt <= qt; kt++) {
        if (kt < qt) { F_FILL(kt + 1, buf ^ 1); cp_wait<1>(); }
        else         { cp_wait<0>(); }
        __syncthreads();
        const float* Ks = Ksb[buf];
        const float* Vs = Vsb[buf];

        // ---- S = Q K^T ----
        float sc[8][4];
        #pragma unroll
        for (int ni = 0; ni < 8; ni++)
            #pragma unroll
            for (int e = 0; e < 4; e++) sc[ni][e] = 0.f;

        #pragma unroll
        for (int kc = 0; kc < 8; kc++) {
            #pragma unroll
            for (int ni = 0; ni < 8; ni++) {
                const float* kr = &Ks[(ni*8 + grp)*KPAD + kc*8 + qid];
                uint32_t bfr[2] = { __float_as_uint(kr[0]), __float_as_uint(kr[4]) };
                mma_tf32(sc[ni], qa[kc], bfr);
            }
        }

        if (kt == qt) {
            const int r0 = qrow0 + grp;
            const int r1 = r0 + 8;
            #pragma unroll
            for (int ni = 0; ni < 8; ni++) {
                const int kg = kt*FQ + ni*8 + 2*qid;
                if (kg     > r0) sc[ni][0] = -1e30f;
                if (kg + 1 > r0) sc[ni][1] = -1e30f;
                if (kg     > r1) sc[ni][2] = -1e30f;
                if (kg + 1 > r1) sc[ni][3] = -1e30f;
            }
        }

        // ---- online softmax ----
        float tm0 = -1e30f, tm1 = -1e30f;
        #pragma unroll
        for (int ni = 0; ni < 8; ni++) {
            tm0 = fmaxf(tm0, fmaxf(sc[ni][0], sc[ni][1]));
            tm1 = fmaxf(tm1, fmaxf(sc[ni][2], sc[ni][3]));
        }
        tm0 = fmaxf(tm0, __shfl_xor_sync(0xffffffffu, tm0, 1));
        tm0 = fmaxf(tm0, __shfl_xor_sync(0xffffffffu, tm0, 2));
        tm1 = fmaxf(tm1, __shfl_xor_sync(0xffffffffu, tm1, 1));
        tm1 = fmaxf(tm1, __shfl_xor_sync(0xffffffffu, tm1, 2));

        const float mn0 = fmaxf(m0, tm0);
        const float mn1 = fmaxf(m1, tm1);
        const float corr0 = __expf(m0 - mn0);
        const float corr1 = __expf(m1 - mn1);
        m0 = mn0; m1 = mn1;

        float ps0 = 0.f, ps1 = 0.f;
        #pragma unroll
        for (int ni = 0; ni < 8; ni++) {
            sc[ni][0] = to_tf32(__expf(sc[ni][0] - mn0));
            sc[ni][1] = to_tf32(__expf(sc[ni][1] - mn0));
            sc[ni][2] = to_tf32(__expf(sc[ni][2] - mn1));
            sc[ni][3] = to_tf32(__expf(sc[ni][3] - mn1));
            ps0 += sc[ni][0] + sc[ni][1];
            ps1 += sc[ni][2] + sc[ni][3];
        }
        ps0 += __shfl_xor_sync(0xffffffffu, ps0, 1);
        ps0 += __shfl_xor_sync(0xffffffffu, ps0, 2);
        ps1 += __shfl_xor_sync(0xffffffffu, ps1, 1);
        ps1 += __shfl_xor_sync(0xffffffffu, ps1, 2);
        l0 = l0*corr0 + ps0;
        l1 = l1*corr1 + ps1;

        #pragma unroll
        for (int ni = 0; ni < 8; ni++) {
            o[ni][0] *= corr0; o[ni][1] *= corr0;
            o[ni][2] *= corr1; o[ni][3] *= corr1;
        }

        // ---- O += P V (P via shuffle: c-layout -> a-layout) ----
        const int sA_ = (lane & ~3) | (qid >> 1);
        const bool hiq = (qid & 1);
        #pragma unroll
        for (int kc = 0; kc < 8; kc++) {
            float e0A = __shfl_sync(0xffffffffu, sc[kc][0], sA_);
            float e1A = __shfl_sync(0xffffffffu, sc[kc][1], sA_);
            float e2A = __shfl_sync(0xffffffffu, sc[kc][2], sA_);
            float e3A = __shfl_sync(0xffffffffu, sc[kc][3], sA_);
            float e0B = __shfl_sync(0xffffffffu, sc[kc][0], sA_ + 2);
            float e1B = __shfl_sync(0xffffffffu, sc[kc][1], sA_ + 2);
            float e2B = __shfl_sync(0xffffffffu, sc[kc][2], sA_ + 2);
            float e3B = __shfl_sync(0xffffffffu, sc[kc][3], sA_ + 2);
            uint32_t pa[4];
            pa[0] = __float_as_uint(hiq ? e1A : e0A);
            pa[1] = __float_as_uint(hiq ? e3A : e2A);
            pa[2] = __float_as_uint(hiq ? e1B : e0B);
            pa[3] = __float_as_uint(hiq ? e3B : e2B);
            #pragma unroll
            for (int ni = 0; ni < 8; ni++) {
                const float* vr = &Vs[(kc*8 + qid)*VPAD + ni*8 + grp];
                uint32_t bfr[2] = { __float_as_uint(vr[0]), __float_as_uint(vr[4*VPAD]) };
                mma_tf32(o[ni], pa, bfr);
            }
        }
        __syncthreads();
        buf ^= 1;
    }
    #undef F_FILL

    // ---- normalize + store O as [B, L, H, HD], tf32-rounded for out_gemm ----
    const float inv0 = 1.f / l0;
    const float inv1 = 1.f / l1;
    const int r0 = qrow0 + grp;
    const int r1 = r0 + 8;
    float* O0 = g_o + (((size_t)(b*L_ + r0))*H_ + h) * HD_;
    float* O1 = g_o + (((size_t)(b*L_ + r1))*H_ + h) * HD_;
    #pragma unroll
    for (int ni = 0; ni < 8; ni++) {
        const int col = ni*8 + 2*qid;
        *(float2*)&O0[col] = make_float2(to_tf32(o[ni][0]*inv0), to_tf32(o[ni][1]*inv0));
        *(float2*)&O1[col] = make_float2(to_tf32(o[ni][2]*inv1), to_tf32(o[ni][3]*inv1));
    }
}

// ============ launch ============
extern "C" void kernel_launch(void* const* d_in, const int* in_sizes, int n_in,
                              void* d_out, int out_size)
{
    const float* hs = (const float*)d_in[0];
    const float* wq = (const float*)d_in[1];
    const float* bq = (const float*)d_in[2];
    const float* wk = (const float*)d_in[3];
    const float* bk = (const float*)d_in[4];
    const float* wv = (const float*)d_in[5];
    const float* bv = (const float*)d_in[6];
    const float* wo = (const float*)d_in[7];
    const float* bo = (const float*)d_in[8];
    float* out = (float*)d_out;

    cudaFuncSetAttribute(qkv_gemm, cudaFuncAttributeMaxDynamicSharedMemorySize, G_SMEM_TOT);
    cudaFuncSetAttribute(out_gemm, cudaFuncAttributeMaxDynamicSharedMemorySize, G_SMEM_TOT);
    cudaFuncSetAttribute(flash_kernel, cudaFuncAttributeMaxDynamicSharedMemorySize, F_SMEM);

    prepass<<<512, 256>>>((const float4*)hs, (const float4*)wq, (const float4*)wk,
                          (const float4*)wv, (const float4*)wo);
    qkv_gemm<<<dim3(9, M_/128), 256, G_SMEM_TOT>>>(bq, bk, bv);
    flash_kernel<<<dim3(L_/FQ, H_*B_), 128, F_SMEM>>>();
    out_gemm<<<dim3(3, M_/128), 256, G_SMEM_TOT>>>(bo, out);
}

// round 7
// speedup vs baseline: 1.6028x; 1.0158x over previous
#include <cuda_runtime.h>
#include <math.h>
#include <stdint.h>

#define B_  4
#define L_  2048
#define H_  12
#define HD_ 64
#define DM_ 768
#define M_  (B_*L_)   // 8192

// Scratch (allocation-free rule: __device__ globals)
// g_x, g_w, g_q, g_k, g_o are stored PAIR-PERMUTED over their k/col dim:
// within each 8-group, element k sits at position ((k&3)<<1)|((k>>2)&1).
// g_v is linear.
__device__ float g_q[B_*H_*L_*HD_];
__device__ float g_k[B_*H_*L_*HD_];
__device__ float g_v[B_*H_*L_*HD_];
__device__ float g_o[M_*DM_];
__device__ float g_x[M_*DM_];
__device__ float g_w[4][DM_*DM_];

// ---------------- helpers ----------------
__device__ __forceinline__ float to_tf32(float x) {
    uint32_t o; asm("cvt.rna.tf32.f32 %0, %1;" : "=r"(o) : "f"(x));
    return __uint_as_float(o);
}
__device__ __forceinline__ int pp8(int k) {        // pair permutation within 8-group
    return ((k & 3) << 1) | ((k >> 2) & 1);
}
__device__ __forceinline__ uint32_t smem_u32(const void* p) {
    uint32_t a;
    asm("{ .reg .u64 t; cvta.to.shared.u64 t, %1; cvt.u32.u64 %0, t; }" : "=r"(a) : "l"(p));
    return a;
}
__device__ __forceinline__ void cp_async16(uint32_t saddr, const void* gptr) {
    asm volatile("cp.async.ca.shared.global [%0], [%1], 16;\n" :: "r"(saddr), "l"(gptr));
}
__device__ __forceinline__ void cp_commit() { asm volatile("cp.async.commit_group;\n"); }
template<int N>
__device__ __forceinline__ void cp_wait() {
    asm volatile("cp.async.wait_group %0;\n" :: "n"(N));
}
__device__ __forceinline__ void mma_tf32(float c[4], const uint32_t a[4], const uint32_t b[2]) {
    asm volatile(
        "mma.sync.aligned.m16n8k8.row.col.f32.tf32.tf32.f32 "
        "{%0,%1,%2,%3}, {%4,%5,%6,%7}, {%8,%9}, {%0,%1,%2,%3};\n"
        : "+f"(c[0]), "+f"(c[1]), "+f"(c[2]), "+f"(c[3])
        : "r"(a[0]), "r"(a[1]), "r"(a[2]), "r"(a[3]), "r"(b[0]), "r"(b[1]));
}

// ---------------- prepass: tf32-round + pair-permute X and W ----------------
__global__ __launch_bounds__(256) void prepass(const float4* __restrict__ hs,
    const float4* __restrict__ wq, const float4* __restrict__ wk,
    const float4* __restrict__ wv, const float4* __restrict__ wo)
{
    const int stride = gridDim.x * blockDim.x;
    const int i0 = blockIdx.x * blockDim.x + threadIdx.x;

    for (int i = i0; i < M_*DM_/4; i += stride) {
        float4 t = hs[i];
        const int row = i / (DM_/4);
        const int k0  = (i - row*(DM_/4)) * 4;            // multiple of 4
        float* dst = g_x + (size_t)row*DM_ + (k0 & ~7);
        const int kb = k0 & 7;                            // 0 or 4
        dst[pp8(kb+0)] = to_tf32(t.x);
        dst[pp8(kb+1)] = to_tf32(t.y);
        dst[pp8(kb+2)] = to_tf32(t.z);
        dst[pp8(kb+3)] = to_tf32(t.w);
    }
    const float4* src[4] = {wq, wk, wv, wo};
    #pragma unroll
    for (int w = 0; w < 4; w++) {
        const float4* s = src[w];
        for (int i = i0; i < DM_*DM_/4; i += stride) {
            float4 t = s[i];
            const int row = i / (DM_/4);
            const int k0  = (i - row*(DM_/4)) * 4;
            float* dst = g_w[w] + (size_t)row*DM_ + (k0 & ~7);
            const int kb = k0 & 7;
            dst[pp8(kb+0)] = to_tf32(t.x);
            dst[pp8(kb+1)] = to_tf32(t.y);
            dst[pp8(kb+2)] = to_tf32(t.z);
            dst[pp8(kb+3)] = to_tf32(t.w);
        }
    }
}

// ---------------- mma.sync tf32 GEMM: C[m,n] = sum_k A[m,k]*W[n,k] + bias[n] ----------------
// 128 threads / 4 warps (2m x 2n), warptile 64x64, CTA 128x128, GBK=16, GPAD=24.
// Operands pair-permuted in global -> fragment pair = one LDS.64, conflict-free.
#define GBK  16
#define GPAD 24

template<bool SCATTER>
__device__ __forceinline__ void tc_gemm(const float* __restrict__ A,
                                        const float* __restrict__ W,
                                        const float* __restrict__ bias,
                                        float* __restrict__ C, int bn, bool paired)
{
    __shared__ float As[2][128*GPAD];   // 12 KB x2
    __shared__ float Ws[2][128*GPAD];   // 12 KB x2  (total 48 KB)

    const int tid = threadIdx.x;          // 0..127
    const int wid = tid >> 5;
    const int lane = tid & 31;
    const int grp = lane >> 2;
    const int qid = lane & 3;
    const int wm = (wid & 1) * 64;
    const int wn = (wid >> 1) * 64;
    const int bm = blockIdx.y * 128;

    float acc[4][8][4];
    #pragma unroll
    for (int mi = 0; mi < 4; mi++)
        #pragma unroll
        for (int ni = 0; ni < 8; ni++)
            #pragma unroll
            for (int e = 0; e < 4; e++) acc[mi][ni][e] = 0.f;

    const int lr = tid >> 2;              // 0..31
    const int c4 = (tid & 3) * 4;         // 0,4,8,12

    #define G_FILL(c, b) do { \
        const float* Ab = A + (size_t)bm * DM_ + (c)*GBK; \
        const float* Wb = W + (size_t)bn * DM_ + (c)*GBK; \
        _Pragma("unroll") \
        for (int hh = 0; hh < 4; hh++) { \
            const int r = lr + hh*32; \
            cp_async16(smem_u32(&As[b][r*GPAD + c4]), Ab + (size_t)r*DM_ + c4); \
            cp_async16(smem_u32(&Ws[b][r*GPAD + c4]), Wb + (size_t)r*DM_ + c4); \
        } \
        cp_commit(); \
    } while (0)

    G_FILL(0, 0);

    const int NC = DM_/GBK;   // 48
    int cur = 0;
    for (int c = 0; c < NC; c++) {
        cp_wait<0>();
        __syncthreads();
        if (c + 1 < NC) G_FILL(c + 1, cur ^ 1);

        #pragma unroll
        for (int kb = 0; kb < 2; kb++) {
            const int kk = kb*8;
            uint32_t af[4][4];
            #pragma unroll
            for (int mi = 0; mi < 4; mi++) {
                const int r0 = wm + mi*16 + grp;
                float2 p0 = *(const float2*)&As[cur][(r0    )*GPAD + kk + 2*qid];
                float2 p1 = *(const float2*)&As[cur][(r0 + 8)*GPAD + kk + 2*qid];
                af[mi][0] = __float_as_uint(p0.x);
                af[mi][1] = __float_as_uint(p1.x);
                af[mi][2] = __float_as_uint(p0.y);
                af[mi][3] = __float_as_uint(p1.y);
            }
            #pragma unroll
            for (int ni = 0; ni < 8; ni++) {
                const int rn = wn + ni*8 + grp;
                float2 pb = *(const float2*)&Ws[cur][rn*GPAD + kk + 2*qid];
                uint32_t bf[2] = { __float_as_uint(pb.x), __float_as_uint(pb.y) };
                #pragma unroll
                for (int mi = 0; mi < 4; mi++)
                    mma_tf32(acc[mi][ni], af[mi], bf);
            }
        }
        cur ^= 1;
    }
    #undef G_FILL

    // epilogue
    #pragma unroll
    for (int mi = 0; mi < 4; mi++) {
        #pragma unroll
        for (int half = 0; half < 2; half++) {
            const int m  = bm + wm + mi*16 + grp + half*8;
            const int bb = m >> 11;
            const int l  = m & (L_ - 1);
            #pragma unroll
            for (int ni = 0; ni < 8; ni++) {
                const int nl = wn + ni*8 + 2*qid;
                const int n  = bn + nl;
                float v0 = acc[mi][ni][half*2 + 0] + bias[n];
                float v1 = acc[mi][ni][half*2 + 1] + bias[n + 1];
                if (SCATTER) {
                    const int hh = n >> 6;
                    const int d  = n & 63;
                    float* dst = &C[(((size_t)bb*H_ + hh)*L_ + l)*HD_ + (d & ~7)];
                    if (paired) {   // Q,K: pair-permuted over head dim
                        dst[pp8(d & 7)]       = to_tf32(v0);
                        dst[pp8((d & 7) + 1)] = to_tf32(v1);
                    } else {        // V: linear
                        *(float2*)&dst[d & 7] = make_float2(to_tf32(v0), to_tf32(v1));
                    }
                } else {
                    *(float2*)&C[(size_t)m*DM_ + n] = make_float2(v0, v1);
                }
            }
        }
    }
}

__global__ __launch_bounds__(128, 3) void qkv_gemm(const float* __restrict__ bq,
                                                   const float* __restrict__ bk,
                                                   const float* __restrict__ bv)
{
    const int z  = blockIdx.z;
    const float* bias = (z == 0) ? bq : (z == 1) ? bk : bv;
    float* out = (z == 0) ? g_q : (z == 1) ? g_k : g_v;
    tc_gemm<true>(g_x, g_w[z], bias, out, blockIdx.x * 128, z != 2);
}

__global__ __launch_bounds__(128, 3) void out_gemm(const float* __restrict__ bo,
                                                   float* __restrict__ out)
{
    tc_gemm<false>(g_o, g_w[3], bo, out, blockIdx.x * 128, false);
}

// ============ causal flash attention ============
// g_q/g_k pair-permuted over head dim; g_v linear. O written pair-permuted to g_o.
#define FQ   64
#define KPAD 72   // paired LDS.64 bank = 4*grp+qid : conflict-free
#define VPAD 72   // scalar LDS bank = 8*qid+grp    : conflict-free
#define F_SMEM ((2*64*KPAD + 2*64*VPAD) * 4)   // 73728

__global__ __launch_bounds__(128, 3) void flash_kernel()
{
    extern __shared__ float fsm[];
    float* Ksb[2] = { fsm,             fsm + 64*KPAD };
    float* Vsb[2] = { fsm + 2*64*KPAD, fsm + 2*64*KPAD + 64*VPAD };
    const uint32_t Ku[2] = { smem_u32(Ksb[0]), smem_u32(Ksb[1]) };
    const uint32_t Vu[2] = { smem_u32(Vsb[0]), smem_u32(Vsb[1]) };

    const int tid  = threadIdx.x;
    const int wid  = tid >> 5;
    const int lane = tid & 31;
    const int grp  = lane >> 2;
    const int qid  = lane & 3;

    const int qt = (int)gridDim.x - 1 - (int)blockIdx.x;  // descending work
    const int h  = blockIdx.y % H_;
    const int b  = blockIdx.y / H_;

    const float* Qb = g_q + (size_t)(b*H_ + h) * L_ * HD_;
    const float* Kb = g_k + (size_t)(b*H_ + h) * L_ * HD_;
    const float* Vb = g_v + (size_t)(b*H_ + h) * L_ * HD_;

    const int qrow0 = qt*FQ + wid*16;
    const float scale = 0.125f;   // exact power of 2

    const int frow = tid >> 4;    // 0..7
    const int fc16 = tid & 15;

    #define F_FILL(kt, bf) do { \
        const float* ksrc = Kb + (size_t)(kt)*FQ*HD_; \
        const float* vsrc = Vb + (size_t)(kt)*FQ*HD_; \
        _Pragma("unroll") \
        for (int it = 0; it < 8; it++) { \
            const int r = frow + it*8; \
            cp_async16(Ku[bf] + r*(KPAD*4) + fc16*16, ksrc + (size_t)r*HD_ + fc16*4); \
            cp_async16(Vu[bf] + r*(VPAD*4) + fc16*16, vsrc + (size_t)r*HD_ + fc16*4); \
        } \
        cp_commit(); \
    } while (0)

    // Q fragments: paired global layout -> LDG.64 pairs
    uint32_t qa[8][4];
    #pragma unroll
    for (int kc = 0; kc < 8; kc++) {
        float2 p0 = *(const float2*)(Qb + (size_t)(qrow0 + grp    )*HD_ + kc*8 + 2*qid);
        float2 p1 = *(const float2*)(Qb + (size_t)(qrow0 + grp + 8)*HD_ + kc*8 + 2*qid);
        qa[kc][0] = __float_as_uint(scale * p0.x);
        qa[kc][1] = __float_as_uint(scale * p1.x);
        qa[kc][2] = __float_as_uint(scale * p0.y);
        qa[kc][3] = __float_as_uint(scale * p1.y);
    }

    float o[8][4];
    #pragma unroll
    for (int ni = 0; ni < 8; ni++)
        #pragma unroll
        for (int e = 0; e < 4; e++) o[ni][e] = 0.f;
    float m0 = -1e30f, m1 = -1e30f, l0 = 0.f, l1 = 0.f;

    F_FILL(0, 0);
    int buf = 0;
    for (int kt = 0; kt <= qt; kt++) {
        cp_wait<0>();
        __syncthreads();
        if (kt < qt) F_FILL(kt + 1, buf ^ 1);
        const float* Ks = Ksb[buf];
        const float* Vs = Vsb[buf];

        // ---- S = Q K^T : b-frag = one conflict-free LDS.64 ----
        float sc[8][4];
        #pragma unroll
        for (int ni = 0; ni < 8; ni++)
            #pragma unroll
            for (int e = 0; e < 4; e++) sc[ni][e] = 0.f;

        #pragma unroll
        for (int kc = 0; kc < 8; kc++) {
            #pragma unroll
            for (int ni = 0; ni < 8; ni++) {
                float2 kf = *(const float2*)&Ks[(ni*8 + grp)*KPAD + kc*8 + 2*qid];
                uint32_t bfr[2] = { __float_as_uint(kf.x), __float_as_uint(kf.y) };
                mma_tf32(sc[ni], qa[kc], bfr);
            }
        }

        if (kt == qt) {
            const int r0 = qrow0 + grp;
            const int r1 = r0 + 8;
            #pragma unroll
            for (int ni = 0; ni < 8; ni++) {
                const int kg = kt*FQ + ni*8 + 2*qid;
                if (kg     > r0) sc[ni][0] = -1e30f;
                if (kg + 1 > r0) sc[ni][1] = -1e30f;
                if (kg     > r1) sc[ni][2] = -1e30f;
                if (kg + 1 > r1) sc[ni][3] = -1e30f;
            }
        }

        // ---- online softmax ----
        float tm0 = -1e30f, tm1 = -1e30f;
        #pragma unroll
        for (int ni = 0; ni < 8; ni++) {
            tm0 = fmaxf(tm0, fmaxf(sc[ni][0], sc[ni][1]));
            tm1 = fmaxf(tm1, fmaxf(sc[ni][2], sc[ni][3]));
        }
        tm0 = fmaxf(tm0, __shfl_xor_sync(0xffffffffu, tm0, 1));
        tm0 = fmaxf(tm0, __shfl_xor_sync(0xffffffffu, tm0, 2));
        tm1 = fmaxf(tm1, __shfl_xor_sync(0xffffffffu, tm1, 1));
        tm1 = fmaxf(tm1, __shfl_xor_sync(0xffffffffu, tm1, 2));

        const float mn0 = fmaxf(m0, tm0);
        const float mn1 = fmaxf(m1, tm1);
        const float corr0 = __expf(m0 - mn0);
        const float corr1 = __expf(m1 - mn1);
        m0 = mn0; m1 = mn1;

        float ps0 = 0.f, ps1 = 0.f;
        #pragma unroll
        for (int ni = 0; ni < 8; ni++) {
            sc[ni][0] = to_tf32(__expf(sc[ni][0] - mn0));
            sc[ni][1] = to_tf32(__expf(sc[ni][1] - mn0));
            sc[ni][2] = to_tf32(__expf(sc[ni][2] - mn1));
            sc[ni][3] = to_tf32(__expf(sc[ni][3] - mn1));
            ps0 += sc[ni][0] + sc[ni][1];
            ps1 += sc[ni][2] + sc[ni][3];
        }
        ps0 += __shfl_xor_sync(0xffffffffu, ps0, 1);
        ps0 += __shfl_xor_sync(0xffffffffu, ps0, 2);
        ps1 += __shfl_xor_sync(0xffffffffu, ps1, 1);
        ps1 += __shfl_xor_sync(0xffffffffu, ps1, 2);
        l0 = l0*corr0 + ps0;
        l1 = l1*corr1 + ps1;

        #pragma unroll
        for (int ni = 0; ni < 8; ni++) {
            o[ni][0] *= corr0; o[ni][1] *= corr0;
            o[ni][2] *= corr1; o[ni][3] *= corr1;
        }

        // ---- O += P V (P via shuffle: c-layout -> a-layout) ----
        const int sA_ = (lane & ~3) | (qid >> 1);
        const bool hiq = (qid & 1);
        #pragma unroll
        for (int kc = 0; kc < 8; kc++) {
            float e0A = __shfl_sync(0xffffffffu, sc[kc][0], sA_);
            float e1A = __shfl_sync(0xffffffffu, sc[kc][1], sA_);
            float e2A = __shfl_sync(0xffffffffu, sc[kc][2], sA_);
            float e3A = __shfl_sync(0xffffffffu, sc[kc][3], sA_);
            float e0B = __shfl_sync(0xffffffffu, sc[kc][0], sA_ + 2);
            float e1B = __shfl_sync(0xffffffffu, sc[kc][1], sA_ + 2);
            float e2B = __shfl_sync(0xffffffffu, sc[kc][2], sA_ + 2);
            float e3B = __shfl_sync(0xffffffffu, sc[kc][3], sA_ + 2);
            uint32_t pa[4];
            pa[0] = __float_as_uint(hiq ? e1A : e0A);
            pa[1] = __float_as_uint(hiq ? e3A : e2A);
            pa[2] = __float_as_uint(hiq ? e1B : e0B);
            pa[3] = __float_as_uint(hiq ? e3B : e2B);
            #pragma unroll
            for (int ni = 0; ni < 8; ni++) {
                const float* vr = &Vs[(kc*8 + qid)*VPAD + ni*8 + grp];
                uint32_t bfr[2] = { __float_as_uint(vr[0]), __float_as_uint(vr[4*VPAD]) };
                mma_tf32(o[ni], pa, bfr);
            }
        }
        buf ^= 1;
    }
    #undef F_FILL

    // ---- normalize + store O pair-permuted (for out_gemm fragment LDS.64) ----
    const float inv0 = 1.f / l0;
    const float inv1 = 1.f / l1;
    const int r0 = qrow0 + grp;
    const int r1 = r0 + 8;
    float* O0 = g_o + (((size_t)(b*L_ + r0))*H_ + h) * HD_;
    float* O1 = g_o + (((size_t)(b*L_ + r1))*H_ + h) * HD_;
    #pragma unroll
    for (int ni = 0; ni < 8; ni++) {
        const int cb = ni*8;
        const int pa_ = pp8(2*qid);
        const int pb_ = pp8(2*qid + 1);
        O0[cb + pa_] = to_tf32(o[ni][0]*inv0);
        O0[cb + pb_] = to_tf32(o[ni][1]*inv0);
        O1[cb + pa_] = to_tf32(o[ni][2]*inv1);
        O1[cb + pb_] = to_tf32(o[ni][3]*inv1);
    }
}

// ============ launch ============
extern "C" void kernel_launch(void* const* d_in, const int* in_sizes, int n_in,
                              void* d_out, int out_size)
{
    const float* hs = (const float*)d_in[0];
    const float* wq = (const float*)d_in[1];
    const float* bq = (const float*)d_in[2];
    const float* wk = (const float*)d_in[3];
    const float* bk = (const float*)d_in[4];
    const float* wv = (const float*)d_in[5];
    const float* bv = (const float*)d_in[6];
    const float* wo = (const float*)d_in[7];
    const float* bo = (const float*)d_in[8];
    float* out = (float*)d_out;

    cudaFuncSetAttribute(flash_kernel, cudaFuncAttributeMaxDynamicSharedMemorySize, F_SMEM);

    prepass<<<768, 256>>>((const float4*)hs, (const float4*)wq, (const float4*)wk,
                          (const float4*)wv, (const float4*)wo);
    qkv_gemm<<<dim3(DM_/128, M_/128, 3), 128>>>(bq, bk, bv);
    flash_kernel<<<dim3(L_/FQ, H_*B_), 128, F_SMEM>>>();
    out_gemm<<<dim3(DM_/128, M_/128), 128>>>(bo, out);
}

// round 8
// speedup vs baseline: 3.9094x; 2.4391x over previous
#include <cuda_runtime.h>
#include <cuda_fp16.h>
#include <math.h>
#include <stdint.h>

#define B_  4
#define L_  2048
#define H_  12
#define HD_ 64
#define DM_ 768
#define M_  (B_*L_)   // 8192

// Scratch (allocation-free rule: __device__ globals), all fp16 operands
__device__ __half g_qh[B_*H_*L_*HD_];   // pre-scaled by 0.125
__device__ __half g_kh[B_*H_*L_*HD_];
__device__ __half g_vh[B_*H_*L_*HD_];
__device__ __half g_oh[M_*DM_];
__device__ __half g_xh[M_*DM_];
__device__ __half g_wh[4][DM_*DM_];

// ---------------- helpers ----------------
__device__ __forceinline__ uint32_t smem_u32(const void* p) {
    uint32_t a;
    asm("{ .reg .u64 t; cvta.to.shared.u64 t, %1; cvt.u32.u64 %0, t; }" : "=r"(a) : "l"(p));
    return a;
}
__device__ __forceinline__ void cp_async16(uint32_t saddr, const void* gptr) {
    asm volatile("cp.async.ca.shared.global [%0], [%1], 16;\n" :: "r"(saddr), "l"(gptr));
}
__device__ __forceinline__ void cp_commit() { asm volatile("cp.async.commit_group;\n"); }
template<int N>
__device__ __forceinline__ void cp_wait() {
    asm volatile("cp.async.wait_group %0;\n" :: "n"(N));
}
__device__ __forceinline__ void mma_f16(float c[4], const uint32_t a[4],
                                        uint32_t b0, uint32_t b1) {
    asm volatile(
        "mma.sync.aligned.m16n8k16.row.col.f32.f16.f16.f32 "
        "{%0,%1,%2,%3}, {%4,%5,%6,%7}, {%8,%9}, {%0,%1,%2,%3};\n"
        : "+f"(c[0]), "+f"(c[1]), "+f"(c[2]), "+f"(c[3])
        : "r"(a[0]), "r"(a[1]), "r"(a[2]), "r"(a[3]), "r"(b0), "r"(b1));
}
__device__ __forceinline__ void ldmx4(uint32_t r[4], uint32_t addr) {
    asm volatile("ldmatrix.sync.aligned.m8n8.x4.shared.b16 {%0,%1,%2,%3}, [%4];"
                 : "=r"(r[0]), "=r"(r[1]), "=r"(r[2]), "=r"(r[3]) : "r"(addr));
}
__device__ __forceinline__ void ldmx4t(uint32_t r[4], uint32_t addr) {
    asm volatile("ldmatrix.sync.aligned.m8n8.x4.trans.shared.b16 {%0,%1,%2,%3}, [%4];"
                 : "=r"(r[0]), "=r"(r[1]), "=r"(r[2]), "=r"(r[3]) : "r"(addr));
}
__device__ __forceinline__ uint32_t pack_h2(float a, float b) {
    __half2 h = __floats2half2_rn(a, b);
    return *(uint32_t*)&h;
}

// ---------------- prepass: convert X and W to fp16 ----------------
__global__ __launch_bounds__(256) void prepass(const float4* __restrict__ hs,
    const float4* __restrict__ wq, const float4* __restrict__ wk,
    const float4* __restrict__ wv, const float4* __restrict__ wo)
{
    const int stride = gridDim.x * blockDim.x;
    const int i0 = blockIdx.x * blockDim.x + threadIdx.x;
    __half2* gx = (__half2*)g_xh;
    for (int i = i0; i < M_*DM_/4; i += stride) {
        float4 t = hs[i];
        gx[2*i]   = __floats2half2_rn(t.x, t.y);
        gx[2*i+1] = __floats2half2_rn(t.z, t.w);
    }
    const float4* src[4] = {wq, wk, wv, wo};
    #pragma unroll
    for (int w = 0; w < 4; w++) {
        __half2* dw = (__half2*)g_wh[w];
        const float4* s = src[w];
        for (int i = i0; i < DM_*DM_/4; i += stride) {
            float4 t = s[i];
            dw[2*i]   = __floats2half2_rn(t.x, t.y);
            dw[2*i+1] = __floats2half2_rn(t.z, t.w);
        }
    }
}

// ---------------- fp16 GEMM: C[m,n] = sum_k A[m,k]*W[n,k] + bias[n] ----------------
// 128 threads / 4 warps (2m x 2n), warptile 64x64, CTA 128x128, GBK=32 halfs/chunk.
#define GBK  32
#define GROW 40   // smem row stride in halfs (80B): conflict-free ldmatrix

template<bool SCATTER>
__device__ __forceinline__ void tc_gemm(const __half* __restrict__ A,
                                        const __half* __restrict__ W,
                                        const float* __restrict__ bias,
                                        __half* __restrict__ Ch,
                                        float* __restrict__ Cf,
                                        int bn, float oscale)
{
    __shared__ __half As[2][128*GROW];
    __shared__ __half Ws[2][128*GROW];

    const int tid = threadIdx.x;          // 0..127
    const int wid = tid >> 5;
    const int lane = tid & 31;
    const int grp = lane >> 2;
    const int qid = lane & 3;
    const int wm = (wid & 1) * 64;
    const int wn = (wid >> 1) * 64;
    const int bm = blockIdx.y * 128;

    // ldmatrix lane offsets
    const int arow = (lane & 7) + ((lane >> 3) & 1) * 8;   // A: m0,m1 rows / m2,m3 rows
    const int acol = (lane >> 4) * 8;                      // A: m2,m3 cols +8
    const int brow = (lane & 7) + ((lane >> 4) << 3);      // B: m2,m3 rows +8
    const int bcol = ((lane >> 3) & 1) * 8;                // B: m1,m3 cols +8

    float acc[4][8][4];
    #pragma unroll
    for (int mi = 0; mi < 4; mi++)
        #pragma unroll
        for (int ni = 0; ni < 8; ni++)
            #pragma unroll
            for (int e = 0; e < 4; e++) acc[mi][ni][e] = 0.f;

    const int fr = tid >> 2;     // 0..31 base row (x4 iters covers 128)
    const int fc = tid & 3;      // 16B chunk (8 halfs)

    #define G_FILL(c, b) do { \
        const __half* Ab = A + (size_t)bm * DM_ + (c)*GBK; \
        const __half* Wb = W + (size_t)bn * DM_ + (c)*GBK; \
        _Pragma("unroll") \
        for (int hh = 0; hh < 4; hh++) { \
            const int r = fr + hh*32; \
            cp_async16(smem_u32(&As[b][r*GROW + fc*8]), Ab + (size_t)r*DM_ + fc*8); \
            cp_async16(smem_u32(&Ws[b][r*GROW + fc*8]), Wb + (size_t)r*DM_ + fc*8); \
        } \
        cp_commit(); \
    } while (0)

    G_FILL(0, 0);

    const int NC = DM_/GBK;   // 24
    int cur = 0;
    for (int c = 0; c < NC; c++) {
        cp_wait<0>();
        __syncthreads();
        if (c + 1 < NC) G_FILL(c + 1, cur ^ 1);

        #pragma unroll
        for (int kb = 0; kb < 2; kb++) {
            const int kk = kb*16;
            uint32_t af[4][4];
            #pragma unroll
            for (int mi = 0; mi < 4; mi++)
                ldmx4(af[mi], smem_u32(&As[cur][(wm + mi*16 + arow)*GROW + kk + acol]));
            #pragma unroll
            for (int nn = 0; nn < 4; nn++) {
                uint32_t bq[4];
                ldmx4(bq, smem_u32(&Ws[cur][(wn + nn*16 + brow)*GROW + kk + bcol]));
                #pragma unroll
                for (int mi = 0; mi < 4; mi++) {
                    mma_f16(acc[mi][2*nn],   af[mi], bq[0], bq[1]);
                    mma_f16(acc[mi][2*nn+1], af[mi], bq[2], bq[3]);
                }
            }
        }
        cur ^= 1;
    }
    #undef G_FILL

    // epilogue (c-layout: rows grp/grp+8, col pairs 2qid)
    #pragma unroll
    for (int mi = 0; mi < 4; mi++) {
        #pragma unroll
        for (int half = 0; half < 2; half++) {
            const int m  = bm + wm + mi*16 + grp + half*8;
            const int bb = m >> 11;
            const int l  = m & (L_ - 1);
            #pragma unroll
            for (int ni = 0; ni < 8; ni++) {
                const int nl = wn + ni*8 + 2*qid;
                const int n  = bn + nl;
                float v0 = (acc[mi][ni][half*2 + 0] + bias[n]) * oscale;
                float v1 = (acc[mi][ni][half*2 + 1] + bias[n + 1]) * oscale;
                if (SCATTER) {
                    const int hh = n >> 6;
                    const int d  = n & 63;
                    *(__half2*)&Ch[(((size_t)bb*H_ + hh)*L_ + l)*HD_ + d] =
                        __floats2half2_rn(v0, v1);
                } else {
                    *(float2*)&Cf[(size_t)m*DM_ + n] = make_float2(v0, v1);
                }
            }
        }
    }
}

__global__ __launch_bounds__(128, 3) void qkv_gemm(const float* __restrict__ bq,
                                                   const float* __restrict__ bk,
                                                   const float* __restrict__ bv)
{
    const int z  = blockIdx.z;
    const float* bias = (z == 0) ? bq : (z == 1) ? bk : bv;
    __half* out = (z == 0) ? g_qh : (z == 1) ? g_kh : g_vh;
    const float sc = (z == 0) ? 0.125f : 1.f;   // fold attn scale into Q
    tc_gemm<true>(g_xh, g_wh[z], bias, out, nullptr, blockIdx.x * 128, sc);
}

__global__ __launch_bounds__(128, 3) void out_gemm(const float* __restrict__ bo,
                                                   float* __restrict__ out)
{
    tc_gemm<false>(g_oh, g_wh[3], bo, nullptr, out, blockIdx.x * 128, 1.f);
}

// ============ causal flash attention, fp16 mma (no P shuffle: C-layout == A-layout) ============
// Q,K,V: [B,H,L,HD] fp16 (Q pre-scaled); O: [B,L,H,HD] fp16.
#define FQ   64
#define FROW 72   // K/V smem row stride in halfs (144B): ldmatrix conflict-free

__global__ __launch_bounds__(128, 3) void flash_kernel()
{
    __shared__ __half Ks[2][64*FROW];
    __shared__ __half Vs[2][64*FROW];
    const uint32_t Ku[2] = { smem_u32(Ks[0]), smem_u32(Ks[1]) };
    const uint32_t Vu[2] = { smem_u32(Vs[0]), smem_u32(Vs[1]) };

    const int tid  = threadIdx.x;
    const int wid  = tid >> 5;
    const int lane = tid & 31;
    const int grp  = lane >> 2;
    const int qid  = lane & 3;

    const int qt = (int)gridDim.x - 1 - (int)blockIdx.x;  // descending work
    const int h  = blockIdx.y % H_;
    const int b  = blockIdx.y / H_;

    const __half* Qb = g_qh + (size_t)(b*H_ + h) * L_ * HD_;
    const __half* Kb = g_kh + (size_t)(b*H_ + h) * L_ * HD_;
    const __half* Vb = g_vh + (size_t)(b*H_ + h) * L_ * HD_;

    const int qrow0 = qt*FQ + wid*16;

    // ldmatrix lane offsets
    const int krow = (lane & 7) + ((lane >> 4) << 3);      // B pattern (keys; m2,m3 +8)
    const int kcol = ((lane >> 3) & 1) * 8;                // d +8 for m1,m3
    const int vrow = (lane & 7) + ((lane >> 3) & 1) * 8;   // trans pattern (keys; m1,m3 +8)
    const int vcol = (lane >> 4) * 8;                      // d +8 for m2,m3

    const int fr = tid >> 3;     // 0..15 base row (x4 iters covers 64)
    const int fc = tid & 7;      // 16B chunk (8 halfs)

    #define F_FILL(kt, bf) do { \
        const __half* ksrc = Kb + (size_t)(kt)*FQ*HD_; \
        const __half* vsrc = Vb + (size_t)(kt)*FQ*HD_; \
        _Pragma("unroll") \
        for (int it = 0; it < 4; it++) { \
            const int r = fr + it*16; \
            cp_async16(Ku[bf] + (r*FROW + fc*8)*2, ksrc + (size_t)r*HD_ + fc*8); \
            cp_async16(Vu[bf] + (r*FROW + fc*8)*2, vsrc + (size_t)r*HD_ + fc*8); \
        } \
        cp_commit(); \
    } while (0)

    // Q fragments (A-layout): 4 k-chunks of 16
    uint32_t qa[4][4];
    #pragma unroll
    for (int kc = 0; kc < 4; kc++) {
        qa[kc][0] = *(const uint32_t*)&Qb[(size_t)(qrow0 + grp    )*HD_ + kc*16 + 2*qid    ];
        qa[kc][1] = *(const uint32_t*)&Qb[(size_t)(qrow0 + grp + 8)*HD_ + kc*16 + 2*qid    ];
        qa[kc][2] = *(const uint32_t*)&Qb[(size_t)(qrow0 + grp    )*HD_ + kc*16 + 2*qid + 8];
        qa[kc][3] = *(const uint32_t*)&Qb[(size_t)(qrow0 + grp + 8)*HD_ + kc*16 + 2*qid + 8];
    }

    float o[8][4];
    #pragma unroll
    for (int ni = 0; ni < 8; ni++)
        #pragma unroll
        for (int e = 0; e < 4; e++) o[ni][e] = 0.f;
    float m0 = -1e30f, m1 = -1e30f, l0 = 0.f, l1 = 0.f;

    F_FILL(0, 0);
    int buf = 0;
    for (int kt = 0; kt <= qt; kt++) {
        cp_wait<0>();
        __syncthreads();
        if (kt < qt) F_FILL(kt + 1, buf ^ 1);

        // ---- S = Q K^T ----
        float sc[8][4];
        #pragma unroll
        for (int ni = 0; ni < 8; ni++)
            #pragma unroll
            for (int e = 0; e < 4; e++) sc[ni][e] = 0.f;

        #pragma unroll
        for (int kc = 0; kc < 4; kc++) {          // d chunks of 16
            #pragma unroll
            for (int nn = 0; nn < 4; nn++) {      // 2 key tiles of 8 each
                uint32_t kb4[4];
                ldmx4(kb4, Ku[buf] + ((nn*16 + krow)*FROW + kc*16 + kcol)*2);
                mma_f16(sc[2*nn],   qa[kc], kb4[0], kb4[1]);
                mma_f16(sc[2*nn+1], qa[kc], kb4[2], kb4[3]);
            }
        }

        if (kt == qt) {
            const int r0 = qrow0 + grp;
            const int r1 = r0 + 8;
            #pragma unroll
            for (int ni = 0; ni < 8; ni++) {
                const int kg = kt*FQ + ni*8 + 2*qid;
                if (kg     > r0) sc[ni][0] = -1e30f;
                if (kg + 1 > r0) sc[ni][1] = -1e30f;
                if (kg     > r1) sc[ni][2] = -1e30f;
                if (kg + 1 > r1) sc[ni][3] = -1e30f;
            }
        }

        // ---- online softmax ----
        float tm0 = -1e30f, tm1 = -1e30f;
        #pragma unroll
        for (int ni = 0; ni < 8; ni++) {
            tm0 = fmaxf(tm0, fmaxf(sc[ni][0], sc[ni][1]));
            tm1 = fmaxf(tm1, fmaxf(sc[ni][2], sc[ni][3]));
        }
        tm0 = fmaxf(tm0, __shfl_xor_sync(0xffffffffu, tm0, 1));
        tm0 = fmaxf(tm0, __shfl_xor_sync(0xffffffffu, tm0, 2));
        tm1 = fmaxf(tm1, __shfl_xor_sync(0xffffffffu, tm1, 1));
        tm1 = fmaxf(tm1, __shfl_xor_sync(0xffffffffu, tm1, 2));

        const float mn0 = fmaxf(m0, tm0);
        const float mn1 = fmaxf(m1, tm1);
        const float corr0 = __expf(m0 - mn0);
        const float corr1 = __expf(m1 - mn1);
        m0 = mn0; m1 = mn1;

        float ps0 = 0.f, ps1 = 0.f;
        #pragma unroll
        for (int ni = 0; ni < 8; ni++) {
            sc[ni][0] = __expf(sc[ni][0] - mn0);
            sc[ni][1] = __expf(sc[ni][1] - mn0);
            sc[ni][2] = __expf(sc[ni][2] - mn1);
            sc[ni][3] = __expf(sc[ni][3] - mn1);
            ps0 += sc[ni][0] + sc[ni][1];
            ps1 += sc[ni][2] + sc[ni][3];
        }
        ps0 += __shfl_xor_sync(0xffffffffu, ps0, 1);
        ps0 += __shfl_xor_sync(0xffffffffu, ps0, 2);
        ps1 += __shfl_xor_sync(0xffffffffu, ps1, 1);
        ps1 += __shfl_xor_sync(0xffffffffu, ps1, 2);
        l0 = l0*corr0 + ps0;
        l1 = l1*corr1 + ps1;

        #pragma unroll
        for (int ni = 0; ni < 8; ni++) {
            o[ni][0] *= corr0; o[ni][1] *= corr0;
            o[ni][2] *= corr1; o[ni][3] *= corr1;
        }

        // ---- O += P V : P packs directly into A-fragments (C-layout == A-layout) ----
        #pragma unroll
        for (int kc = 0; kc < 4; kc++) {          // key chunks of 16
            uint32_t pa[4];
            pa[0] = pack_h2(sc[2*kc  ][0], sc[2*kc  ][1]);
            pa[1] = pack_h2(sc[2*kc  ][2], sc[2*kc  ][3]);
            pa[2] = pack_h2(sc[2*kc+1][0], sc[2*kc+1][1]);
            pa[3] = pack_h2(sc[2*kc+1][2], sc[2*kc+1][3]);
            #pragma unroll
            for (int nn = 0; nn < 4; nn++) {      // 2 d tiles of 8 each
                uint32_t vb4[4];
                ldmx4t(vb4, Vu[buf] + ((kc*16 + vrow)*FROW + nn*16 + vcol)*2);
                mma_f16(o[2*nn],   pa, vb4[0], vb4[1]);
                mma_f16(o[2*nn+1], pa, vb4[2], vb4[3]);
            }
        }
        buf ^= 1;
    }
    #undef F_FILL

    // ---- normalize + store O as fp16 [B, L, H, HD] ----
    const float inv0 = 1.f / l0;
    const float inv1 = 1.f / l1;
    const int r0 = qrow0 + grp;
    const int r1 = r0 + 8;
    __half* O0 = g_oh + (((size_t)(b*L_ + r0))*H_ + h) * HD_;
    __half* O1 = g_oh + (((size_t)(b*L_ + r1))*H_ + h) * HD_;
    #pragma unroll
    for (int ni = 0; ni < 8; ni++) {
        const int col = ni*8 + 2*qid;
        *(__half2*)&O0[col] = __floats2half2_rn(o[ni][0]*inv0, o[ni][1]*inv0);
        *(__half2*)&O1[col] = __floats2half2_rn(o[ni][2]*inv1, o[ni][3]*inv1);
    }
}

// ============ launch ============
extern "C" void kernel_launch(void* const* d_in, const int* in_sizes, int n_in,
                              void* d_out, int out_size)
{
    const float* hs = (const float*)d_in[0];
    const float* wq = (const float*)d_in[1];
    const float* bq = (const float*)d_in[2];
    const float* wk = (const float*)d_in[3];
    const float* bk = (const float*)d_in[4];
    const float* wv = (const float*)d_in[5];
    const float* bv = (const float*)d_in[6];
    const float* wo = (const float*)d_in[7];
    const float* bo = (const float*)d_in[8];
    float* out = (float*)d_out;

    prepass<<<768, 256>>>((const float4*)hs, (const float4*)wq, (const float4*)wk,
                          (const float4*)wv, (const float4*)wo);
    qkv_gemm<<<dim3(DM_/128, M_/128, 3), 128>>>(bq, bk, bv);
    flash_kernel<<<dim3(L_/FQ, H_*B_), 128>>>();
    out_gemm<<<dim3(DM_/128, M_/128), 128>>>(bo, out);
}